// round 13
// baseline (speedup 1.0000x reference)
#include <cuda_runtime.h>
#include <cuda_fp16.h>
#include <math.h>
#include <stdint.h>

// Problem constants
#define BB   2
#define HH   128
#define WWID 128
#define CC   128
#define NWIN 64
#define WSZ  256
#define LTOK (HH*WWID)     // 16384
#define ROWS (BB*LTOK)     // 32768
#define HIDN 1024

// ---------------- scratch ---------------------------------------------------
__device__ __half g_QW[ROWS*CC];
__device__ __half g_KW[ROWS*CC];
__device__ __half g_VW[ROWS*CC];
__device__ __half g_VWt[ROWS*CC];          // per-window transposed V: [wb][dim][key]
__device__ __half g_ATT[ROWS*CC];
__device__ float  g_MSG[ROWS*CC];          // fp32 (feeds LayerNorm)
__device__ __half g_FIN[(size_t)ROWS*2*CC];
__device__ __half g_HID[(size_t)ROWS*HIDN];
// transposed weights [N, K] in fp16
__device__ __half g_WqkvT[3*CC*CC];        // [WqT ; WkT ; WvT]
__device__ __half g_WmT[CC*CC];
__device__ __half g_W1T[HIDN*2*CC];
__device__ __half g_W2T[CC*HIDN];

// ---------------- helpers ---------------------------------------------------
__device__ __forceinline__ float gelu_exact(float x) {
    return 0.5f * x * (1.0f + erff(x * 0.70710678118654752f));
}
__device__ __forceinline__ uint32_t smem_u32(const void* p) {
    uint32_t a;
    asm("{ .reg .u64 t; cvta.to.shared.u64 t, %1; cvt.u32.u64 %0, t; }" : "=r"(a) : "l"(p));
    return a;
}
__device__ __forceinline__ void cpasync16(uint32_t dst, const __half* src) {
    asm volatile("cp.async.cg.shared.global [%0], [%1], 16;" :: "r"(dst), "l"(src));
}
#define CP_COMMIT() asm volatile("cp.async.commit_group;")
#define CP_WAIT0()  asm volatile("cp.async.wait_group 0;")
__device__ __forceinline__ void ldmx4(uint32_t addr, uint32_t& d0, uint32_t& d1,
                                      uint32_t& d2, uint32_t& d3) {
    asm volatile("ldmatrix.sync.aligned.m8n8.x4.shared.b16 {%0,%1,%2,%3}, [%4];"
                 : "=r"(d0), "=r"(d1), "=r"(d2), "=r"(d3) : "r"(addr));
}
__device__ __forceinline__ void mma_h(float* c, const uint32_t* a, uint32_t b0, uint32_t b1) {
    asm volatile("mma.sync.aligned.m16n8k16.row.col.f32.f16.f16.f32 "
                 "{%0,%1,%2,%3}, {%4,%5,%6,%7}, {%8,%9}, {%0,%1,%2,%3};"
                 : "+f"(c[0]), "+f"(c[1]), "+f"(c[2]), "+f"(c[3])
                 : "r"(a[0]), "r"(a[1]), "r"(a[2]), "r"(a[3]), "r"(b0), "r"(b1));
}

// ---------------- batched weight transpose: fp32 [R,C] -> fp16 [C,R] --------
__global__ __launch_bounds__(256) void transpose_all(const float* __restrict__ Wq,
                                                     const float* __restrict__ Wk,
                                                     const float* __restrict__ Wv,
                                                     const float* __restrict__ Wm,
                                                     const float* __restrict__ W1,
                                                     const float* __restrict__ W2)
{
    __shared__ float t[32][33];
    int id = blockIdx.x;
    const float* src; __half* dst; int R, C, bx, by;
    if (id < 64) {
        int wsel = id >> 4, tt = id & 15;
        bx = tt & 3; by = tt >> 2; R = 128; C = 128;
        src = (wsel == 0) ? Wq : (wsel == 1) ? Wk : (wsel == 2) ? Wv : Wm;
        dst = (wsel == 0) ? g_WqkvT : (wsel == 1) ? (g_WqkvT + 128 * 128)
            : (wsel == 2) ? (g_WqkvT + 2 * 128 * 128) : g_WmT;
    } else if (id < 320) {
        int tt = id - 64; bx = tt & 31; by = tt >> 5; R = 256; C = 1024;
        src = W1; dst = g_W1T;
    } else {
        int tt = id - 320; bx = tt & 3; by = tt >> 2; R = 1024; C = 128;
        src = W2; dst = g_W2T;
    }
    int tx = threadIdx.x, ty = threadIdx.y;
    int x = bx * 32 + tx;
    #pragma unroll
    for (int i = 0; i < 32; i += 8)
        t[ty + i][tx] = src[(size_t)(by * 32 + ty + i) * C + x];
    __syncthreads();
    int x2 = by * 32 + tx;
    #pragma unroll
    for (int i = 0; i < 32; i += 8)
        dst[(size_t)(bx * 32 + ty + i) * R + x2] = __float2half(t[tx][ty + i]);
}

// ---------------- per-window V transpose (fp16) -----------------------------
__global__ __launch_bounds__(256) void vtrans_kernel()
{
    __shared__ __half t[32][34];
    int wb = blockIdx.z;
    int d0 = blockIdx.x * 32, k0 = blockIdx.y * 32;
    int tx = threadIdx.x, ty = threadIdx.y;
    const __half* src = g_VW + (size_t)wb * 32768;
    #pragma unroll
    for (int i = 0; i < 32; i += 8)
        t[ty + i][tx] = src[(size_t)(k0 + ty + i) * 128 + d0 + tx];
    __syncthreads();
    __half* dst = g_VWt + (size_t)wb * 32768;
    #pragma unroll
    for (int i = 0; i < 32; i += 8)
        dst[(size_t)(d0 + ty + i) * 256 + k0 + tx] = t[tx][ty + i];
}

// ---------------- one-shot K=128 GEMM ---------------------------------------
#define P1 136
#define G128_SMEM (2*128*P1*2)   // 69632

template<int PERM, int OUTH>
__global__ __launch_bounds__(256, 2) void gemm128(const void* __restrict__ A0v,
                                                  const void* __restrict__ A1v,
                                                  const __half* __restrict__ Bt,
                                                  void* __restrict__ C0v,
                                                  void* __restrict__ C1v,
                                                  void* __restrict__ C2v)
{
    extern __shared__ __half smh[];
    __half* sA  = smh;             // [128][136]
    __half* sBt = smh + 128 * P1;  // [128][136]
    int tid = threadIdx.x, wid = tid >> 5, lane = tid & 31;
    int wm = wid & 3, wn = wid >> 2;
    size_t m0 = (size_t)blockIdx.y * 128;
    int nb = blockIdx.x;

    #pragma unroll
    for (int i = 0; i < 8; i++) {
        int idx = tid + i * 256;
        int row = idx >> 4, c8 = (idx & 15) * 8;
        cpasync16(smem_u32(sBt + row * P1 + c8),
                  Bt + (size_t)(nb * 128 + row) * 128 + c8);
    }
    CP_COMMIT();

    if (PERM) {
        const float* Af = (nb == 0) ? (const float*)A0v : (const float*)A1v;
        int r2 = tid >> 1, hh = tid & 1;
        size_t m = m0 + r2;
        int b = (int)(m >> 14), win = (int)((m >> 8) & 63), pos = (int)(m & 255);
        int ip = ((win >> 3) << 4) + (pos >> 4);
        int jp = ((win & 7) << 4) + (pos & 15);
        int ii = (ip + 8) & 127, jj = (jp + 8) & 127;
        const float* srow = Af + ((size_t)b * LTOK + (size_t)ii * 128 + jj) * 128 + hh * 64;
        __half* drow = sA + r2 * P1 + hh * 64;
        #pragma unroll
        for (int q = 0; q < 16; q++) {
            float4 v = *(const float4*)(srow + q * 4);
            *(__half2*)(drow + q * 4)     = __floats2half2_rn(v.x, v.y);
            *(__half2*)(drow + q * 4 + 2) = __floats2half2_rn(v.z, v.w);
        }
    } else {
        const __half* Ah = (const __half*)A0v;
        #pragma unroll
        for (int i = 0; i < 8; i++) {
            int idx = tid + i * 256;
            int row = idx >> 4, c8 = (idx & 15) * 8;
            cpasync16(smem_u32(sA + row * P1 + c8), Ah + (m0 + row) * 128 + c8);
        }
        CP_COMMIT();
    }
    CP_WAIT0();
    __syncthreads();

    float acc[2][8][4] = {};
    int mat = lane >> 3, mr = lane & 7;
    int a_row = wm * 32 + (mat & 1) * 8 + mr;
    int a_k8  = (mat >> 1) * 8;
    int b_n   = wn * 64 + (mat >> 1) * 8 + mr;
    int b_k8  = (mat & 1) * 8;
    uint32_t uA = smem_u32(sA), uB = smem_u32(sBt);

    #pragma unroll
    for (int ks = 0; ks < 8; ks++) {
        uint32_t a[2][4], bb[4][4];
        #pragma unroll
        for (int mt = 0; mt < 2; mt++)
            ldmx4(uA + (uint32_t)(((a_row + mt * 16) * P1 + ks * 16 + a_k8) * 2),
                  a[mt][0], a[mt][1], a[mt][2], a[mt][3]);
        #pragma unroll
        for (int h = 0; h < 4; h++)
            ldmx4(uB + (uint32_t)(((b_n + h * 16) * P1 + ks * 16 + b_k8) * 2),
                  bb[h][0], bb[h][1], bb[h][2], bb[h][3]);
        #pragma unroll
        for (int mt = 0; mt < 2; mt++)
            #pragma unroll
            for (int nt = 0; nt < 8; nt++)
                mma_h(acc[mt][nt], a[mt],
                      bb[nt >> 1][(nt & 1) * 2], bb[nt >> 1][(nt & 1) * 2 + 1]);
    }

    void* Cv = (nb == 0) ? C0v : (nb == 1) ? C1v : C2v;
    int er = lane >> 2, ec = (lane & 3) * 2;
    #pragma unroll
    for (int mt = 0; mt < 2; mt++) {
        size_t r0 = m0 + wm * 32 + mt * 16 + er;
        #pragma unroll
        for (int nt = 0; nt < 8; nt++) {
            int c0 = wn * 64 + nt * 8 + ec;
            if (OUTH) {
                __half* C = (__half*)Cv;
                *(__half2*)(C + r0 * 128 + c0) =
                    __floats2half2_rn(acc[mt][nt][0], acc[mt][nt][1]);
                *(__half2*)(C + (r0 + 8) * 128 + c0) =
                    __floats2half2_rn(acc[mt][nt][2], acc[mt][nt][3]);
            } else {
                float* C = (float*)Cv;
                *(float2*)(C + r0 * 128 + c0) =
                    make_float2(acc[mt][nt][0], acc[mt][nt][1]);
                *(float2*)(C + (r0 + 8) * 128 + c0) =
                    make_float2(acc[mt][nt][2], acc[mt][nt][3]);
            }
        }
    }
}

// ---------------- big-K GEMM: 2-stage cp.async, K-chunk 64 ------------------
// 128 threads / 4 warps (2m x 2n), warp tile 64x64: halves per-CTA smem reads
// (A re-read x2, B x2 instead of x2/x4) -> crossbar-bound mainloop speeds up.
#define P2 72
#define ST_ELEMS (128*P2)
#define BIG_SMEM (2*2*ST_ELEMS*2)   // 73728

__device__ __forceinline__ void big_load_stage(__half* smh, int s,
                                               const __half* __restrict__ A,
                                               const __half* __restrict__ Bt,
                                               size_t m0, int n0, int K, int kc, int tid)
{
    __half* dA = smh + s * 2 * ST_ELEMS;
    __half* dB = dA + ST_ELEMS;
    #pragma unroll
    for (int i = 0; i < 8; i++) {
        int idx = tid + i * 128;
        int row = idx >> 3, c8 = (idx & 7) * 8;
        cpasync16(smem_u32(dA + row * P2 + c8), A  + (m0 + row) * (size_t)K + kc * 64 + c8);
        cpasync16(smem_u32(dB + row * P2 + c8), Bt + (size_t)(n0 + row) * K + kc * 64 + c8);
    }
    CP_COMMIT();
}

__device__ __forceinline__ void big_mainloop(__half* smh, const __half* A,
                                             const __half* Bt, size_t m0, int n0,
                                             int K, int tid, float acc[4][8][4])
{
    int lane = tid & 31, wid = tid >> 5;
    int wm = wid & 1, wn = wid >> 1;           // 2m x 2n warps, 64x64 tiles
    int mat = lane >> 3, mr = lane & 7;
    int a_row = wm * 64 + (mat & 1) * 8 + mr;  // + mt*16
    int a_k8  = (mat >> 1) * 8;
    int b_n   = wn * 64 + (mat >> 1) * 8 + mr; // + h*16
    int b_k8  = (mat & 1) * 8;
    const int nk = K >> 6;

    big_load_stage(smh, 0, A, Bt, m0, n0, K, 0, tid);

    for (int kt = 0; kt < nk; kt++) {
        CP_WAIT0();
        __syncthreads();
        if (kt + 1 < nk)
            big_load_stage(smh, (kt + 1) & 1, A, Bt, m0, n0, K, kt + 1, tid);

        int s = kt & 1;
        uint32_t uA = smem_u32(smh + s * 2 * ST_ELEMS);
        uint32_t uB = smem_u32(smh + s * 2 * ST_ELEMS + ST_ELEMS);
        #pragma unroll
        for (int ks = 0; ks < 4; ks++) {
            uint32_t a[4][4], bb[4][4];
            #pragma unroll
            for (int mt = 0; mt < 4; mt++)
                ldmx4(uA + (uint32_t)(((a_row + mt * 16) * P2 + ks * 16 + a_k8) * 2),
                      a[mt][0], a[mt][1], a[mt][2], a[mt][3]);
            #pragma unroll
            for (int h = 0; h < 4; h++)
                ldmx4(uB + (uint32_t)(((b_n + h * 16) * P2 + ks * 16 + b_k8) * 2),
                      bb[h][0], bb[h][1], bb[h][2], bb[h][3]);
            #pragma unroll
            for (int mt = 0; mt < 4; mt++)
                #pragma unroll
                for (int nt = 0; nt < 8; nt++)
                    mma_h(acc[mt][nt], a[mt],
                          bb[nt >> 1][(nt & 1) * 2], bb[nt >> 1][(nt & 1) * 2 + 1]);
        }
        __syncthreads();
    }
}

// FFN1: fp16 out with gelu
__global__ __launch_bounds__(128, 2) void gemm_big_gelu(const __half* __restrict__ A,
                                                        const __half* __restrict__ Bt,
                                                        __half* __restrict__ C,
                                                        int N, int K)
{
    extern __shared__ __half smh[];
    int tid = threadIdx.x, wid = tid >> 5, lane = tid & 31;
    int wm = wid & 1, wn = wid >> 1;
    size_t m0 = (size_t)blockIdx.y * 128;
    int n0 = blockIdx.x * 128;

    float acc[4][8][4] = {};
    big_mainloop(smh, A, Bt, m0, n0, K, tid, acc);

    int er = lane >> 2, ec = (lane & 3) * 2;
    #pragma unroll
    for (int mt = 0; mt < 4; mt++) {
        size_t r0 = m0 + wm * 64 + mt * 16 + er;
        #pragma unroll
        for (int nt = 0; nt < 8; nt++) {
            int c0 = n0 + wn * 64 + nt * 8 + ec;
            float v0 = gelu_exact(acc[mt][nt][0]);
            float v1 = gelu_exact(acc[mt][nt][1]);
            float v2 = gelu_exact(acc[mt][nt][2]);
            float v3 = gelu_exact(acc[mt][nt][3]);
            *(__half2*)(C + r0 * N + c0)       = __floats2half2_rn(v0, v1);
            *(__half2*)(C + (r0 + 8) * N + c0) = __floats2half2_rn(v2, v3);
        }
    }
}

// FFN2: fused LayerNorm + residual -> fp32 d_out (N == 128, grid.x == 1)
#define CPAD 132
__global__ __launch_bounds__(128, 2) void gemm_big_lnres(const __half* __restrict__ A,
                                                         const __half* __restrict__ Bt,
                                                         float* __restrict__ out,
                                                         int K,
                                                         const float* __restrict__ src,
                                                         const float* __restrict__ g2,
                                                         const float* __restrict__ b2)
{
    extern __shared__ __half smh[];
    int tid = threadIdx.x, wid = tid >> 5, lane = tid & 31;
    int wm = wid & 1, wn = wid >> 1;
    size_t m0 = (size_t)blockIdx.y * 128;

    float acc[4][8][4] = {};
    big_mainloop(smh, A, Bt, m0, 0, K, tid, acc);

    float* Cs = (float*)smh;   // [128][132] = 67584 B <= 73728
    int er = lane >> 2, ec = (lane & 3) * 2;
    #pragma unroll
    for (int mt = 0; mt < 4; mt++) {
        int r0l = wm * 64 + mt * 16 + er;
        #pragma unroll
        for (int nt = 0; nt < 8; nt++) {
            int c0 = wn * 64 + nt * 8 + ec;
            Cs[r0l * CPAD + c0]           = acc[mt][nt][0];
            Cs[r0l * CPAD + c0 + 1]       = acc[mt][nt][1];
            Cs[(r0l + 8) * CPAD + c0]     = acc[mt][nt][2];
            Cs[(r0l + 8) * CPAD + c0 + 1] = acc[mt][nt][3];
        }
    }
    __syncthreads();

    for (int rr = wid; rr < 128; rr += 4) {
        float4 mv = *(const float4*)(Cs + rr * CPAD + lane * 4);
        float s  = mv.x + mv.y + mv.z + mv.w;
        float ss = mv.x * mv.x + mv.y * mv.y + mv.z * mv.z + mv.w * mv.w;
        #pragma unroll
        for (int o = 16; o > 0; o >>= 1) {
            s  += __shfl_xor_sync(0xffffffffu, s,  o);
            ss += __shfl_xor_sync(0xffffffffu, ss, o);
        }
        float mean = s * (1.0f / 128.0f);
        float var  = ss * (1.0f / 128.0f) - mean * mean;
        float r = rsqrtf(var + 1e-5f);
        float4 gv = ((const float4*)g2)[lane];
        float4 bv = ((const float4*)b2)[lane];
        size_t row = m0 + rr;
        float4 sv = ((const float4*)(src + row * 128))[lane];
        float4 o4;
        o4.x = sv.x + (mv.x - mean) * r * gv.x + bv.x;
        o4.y = sv.y + (mv.y - mean) * r * gv.y + bv.y;
        o4.z = sv.z + (mv.z - mean) * r * gv.z + bv.z;
        o4.w = sv.w + (mv.w - mean) * r * gv.w + bv.w;
        ((float4*)(out + row * 128))[lane] = o4;
    }
}

// ---------------- windowed attention: register-resident scores (R12) --------
#define AQ 0
#define AK 8704
#define AP 43520
#define ARX 60416
#define ARS 60928
#define AT_SMEM_BYTES 61440

__device__ __forceinline__ int region3(int x) { return (x < 112) ? 0 : ((x < 120) ? 1 : 2); }
__device__ __forceinline__ int posid(int p, int wr, int wc) {
    return region3(wr * 16 + (p >> 4)) * 3 + region3(wc * 16 + (p & 15));
}

__global__ __launch_bounds__(256, 3) void attn_mma()
{
    extern __shared__ char sm[];
    uint32_t sB = smem_u32(sm);
    __half* Qs = (__half*)(sm + AQ);
    __half* KVs = (__half*)(sm + AK);
    __half* Ps = (__half*)(sm + AP);
    float*  Rmx = (float*)(sm + ARX);
    float*  Rsm = (float*)(sm + ARS);

    const int tid = threadIdx.x;
    const int lane = tid & 31, w = tid >> 5;
    const int wb = blockIdx.x >> 3, oct = blockIdx.x & 7;
    const int q0 = oct * 32;
    const int win = wb & 63, wr = win >> 3, wc = win & 7;
    const size_t wbase = (size_t)wb * 256 * 128;

    const int wm = w & 1, wn = w >> 1;
    const int mat = lane >> 3, mr = lane & 7;
    const int a_row = wm * 16 + (mat & 1) * 8 + mr;
    const int a_k8  = (mat >> 1) * 8;
    const int bn_off = (mat >> 1) * 8 + mr;
    const int b_k8   = (mat & 1) * 8;
    const int er = lane >> 2, ec = (lane & 3) * 2;

    #pragma unroll
    for (int i = 0; i < 2; i++) {
        int idx = tid + i * 256;
        int row = idx >> 4, c8 = (idx & 15) * 8;
        *(uint4*)(Qs + row * 136 + c8) =
            *(const uint4*)(g_QW + wbase + (size_t)(q0 + row) * 128 + c8);
    }

    const int rq = wm * 16 + er;
    const int idq0 = posid(q0 + rq, wr, wc);
    const int idq1 = posid(q0 + rq + 8, wr, wc);
    const float SC = 0.08838834764831845f;

    float sacc[2][4][4] = {};
    for (int kb = 0; kb < 2; kb++) {
        __syncthreads();
        #pragma unroll
        for (int i = 0; i < 8; i++) {
            int idx = tid + i * 256;
            int row = idx >> 4, c8 = (idx & 15) * 8;
            *(uint4*)(KVs + row * 136 + c8) =
                *(const uint4*)(g_KW + wbase + (size_t)(kb * 128 + row) * 128 + c8);
        }
        __syncthreads();

        #pragma unroll
        for (int ks = 0; ks < 8; ks++) {
            uint32_t a[4], bbf[2][4];
            ldmx4(sB + (uint32_t)(AQ + (a_row * 136 + ks * 16 + a_k8) * 2),
                  a[0], a[1], a[2], a[3]);
            #pragma unroll
            for (int h = 0; h < 2; h++)
                ldmx4(sB + (uint32_t)(AK + ((wn * 32 + h * 16 + bn_off) * 136 + ks * 16 + b_k8) * 2),
                      bbf[h][0], bbf[h][1], bbf[h][2], bbf[h][3]);
            #pragma unroll
            for (int nt = 0; nt < 4; nt++)
                mma_h(sacc[kb][nt], a, bbf[nt >> 1][(nt & 1) * 2], bbf[nt >> 1][(nt & 1) * 2 + 1]);
        }
    }

    float m0 = -1e30f, m1 = -1e30f;
    #pragma unroll
    for (int kb = 0; kb < 2; kb++)
        #pragma unroll
        for (int nt = 0; nt < 4; nt++) {
            int key = kb * 128 + wn * 32 + nt * 8 + ec;
            int idk0 = posid(key, wr, wc), idk1 = posid(key + 1, wr, wc);
            float s0 = sacc[kb][nt][0] * SC + ((idq0 == idk0) ? 0.f : -100.f);
            float s1 = sacc[kb][nt][1] * SC + ((idq0 == idk1) ? 0.f : -100.f);
            float s2 = sacc[kb][nt][2] * SC + ((idq1 == idk0) ? 0.f : -100.f);
            float s3 = sacc[kb][nt][3] * SC + ((idq1 == idk1) ? 0.f : -100.f);
            sacc[kb][nt][0] = s0; sacc[kb][nt][1] = s1;
            sacc[kb][nt][2] = s2; sacc[kb][nt][3] = s3;
            m0 = fmaxf(m0, fmaxf(s0, s1));
            m1 = fmaxf(m1, fmaxf(s2, s3));
        }
    m0 = fmaxf(m0, __shfl_xor_sync(0xffffffffu, m0, 1));
    m0 = fmaxf(m0, __shfl_xor_sync(0xffffffffu, m0, 2));
    m1 = fmaxf(m1, __shfl_xor_sync(0xffffffffu, m1, 1));
    m1 = fmaxf(m1, __shfl_xor_sync(0xffffffffu, m1, 2));
    if ((lane & 3) == 0) {
        Rmx[rq * 4 + wn]       = m0;
        Rmx[(rq + 8) * 4 + wn] = m1;
    }
    __syncthreads();
    m0 = fmaxf(fmaxf(Rmx[rq * 4 + 0], Rmx[rq * 4 + 1]),
               fmaxf(Rmx[rq * 4 + 2], Rmx[rq * 4 + 3]));
    m1 = fmaxf(fmaxf(Rmx[(rq + 8) * 4 + 0], Rmx[(rq + 8) * 4 + 1]),
               fmaxf(Rmx[(rq + 8) * 4 + 2], Rmx[(rq + 8) * 4 + 3]));

    float s0sum = 0.f, s1sum = 0.f;
    #pragma unroll
    for (int kb = 0; kb < 2; kb++)
        #pragma unroll
        for (int nt = 0; nt < 4; nt++) {
            int key = kb * 128 + wn * 32 + nt * 8 + ec;
            float e0 = __expf(sacc[kb][nt][0] - m0);
            float e1 = __expf(sacc[kb][nt][1] - m0);
            float e2 = __expf(sacc[kb][nt][2] - m1);
            float e3 = __expf(sacc[kb][nt][3] - m1);
            s0sum += e0 + e1;
            s1sum += e2 + e3;
            *(__half2*)(Ps + rq * 264 + key)       = __floats2half2_rn(e0, e1);
            *(__half2*)(Ps + (rq + 8) * 264 + key) = __floats2half2_rn(e2, e3);
        }
    s0sum += __shfl_xor_sync(0xffffffffu, s0sum, 1);
    s0sum += __shfl_xor_sync(0xffffffffu, s0sum, 2);
    s1sum += __shfl_xor_sync(0xffffffffu, s1sum, 1);
    s1sum += __shfl_xor_sync(0xffffffffu, s1sum, 2);
    if ((lane & 3) == 0) {
        Rsm[rq * 4 + wn]       = s0sum;
        Rsm[(rq + 8) * 4 + wn] = s1sum;
    }
    __syncthreads();
    float inv0 = 1.0f / (Rsm[rq * 4 + 0] + Rsm[rq * 4 + 1]
                       + Rsm[rq * 4 + 2] + Rsm[rq * 4 + 3]);
    float inv1 = 1.0f / (Rsm[(rq + 8) * 4 + 0] + Rsm[(rq + 8) * 4 + 1]
                       + Rsm[(rq + 8) * 4 + 2] + Rsm[(rq + 8) * 4 + 3]);

    float oacc[4][4] = {};
    for (int kb = 0; kb < 2; kb++) {
        if (kb) __syncthreads();
        #pragma unroll
        for (int i = 0; i < 8; i++) {
            int idx = tid + i * 256;
            int row = idx >> 4, c8 = (idx & 15) * 8;
            *(uint4*)(KVs + row * 136 + c8) =
                *(const uint4*)(g_VWt + (size_t)wb * 32768 + (size_t)row * 256 + kb * 128 + c8);
        }
        __syncthreads();

        #pragma unroll
        for (int ks = 0; ks < 8; ks++) {
            uint32_t a[4], bv[2][4];
            ldmx4(sB + (uint32_t)(AP + (a_row * 264 + kb * 128 + ks * 16 + a_k8) * 2),
                  a[0], a[1], a[2], a[3]);
            #pragma unroll
            for (int h = 0; h < 2; h++)
                ldmx4(sB + (uint32_t)(AK + ((wn * 32 + h * 16 + bn_off) * 136 + ks * 16 + b_k8) * 2),
                      bv[h][0], bv[h][1], bv[h][2], bv[h][3]);
            #pragma unroll
            for (int nt = 0; nt < 4; nt++)
                mma_h(oacc[nt], a, bv[nt >> 1][(nt & 1) * 2], bv[nt >> 1][(nt & 1) * 2 + 1]);
        }
    }

    {
        __half* op = g_ATT + wbase + (size_t)(q0 + rq) * 128;
        #pragma unroll
        for (int nt = 0; nt < 4; nt++) {
            int dim = wn * 32 + nt * 8 + ec;
            *(__half2*)(op + dim) =
                __floats2half2_rn(oacc[nt][0] * inv0, oacc[nt][1] * inv0);
            *(__half2*)(op + 8 * 128 + dim) =
                __floats2half2_rn(oacc[nt][2] * inv1, oacc[nt][3] * inv1);
        }
    }
}

// ---------------- LN(msg) + un-shift gather + concat (fp16 out) -------------
__global__ __launch_bounds__(256) void ln_concat_kernel(const float* __restrict__ src,
                                                        const float* __restrict__ g1,
                                                        const float* __restrict__ b1)
{
    int warp = (blockIdx.x * 256 + threadIdx.x) >> 5;
    int lane = threadIdx.x & 31;
    if (warp >= ROWS) return;
    int b   = warp >> 14;
    int tok = warp & 16383;
    int i = tok >> 7, j = tok & 127;
    int ip = (i + 120) & 127;
    int jp = (j + 120) & 127;
    int win = ((ip >> 4) << 3) + (jp >> 4);
    int pos = ((ip & 15) << 4) + (jp & 15);
    size_t mrow = ((size_t)b * NWIN + win) * WSZ + pos;

    float4 mv = ((const float4*)(g_MSG + mrow * CC))[lane];
    float s  = mv.x + mv.y + mv.z + mv.w;
    float ss = mv.x * mv.x + mv.y * mv.y + mv.z * mv.z + mv.w * mv.w;
    #pragma unroll
    for (int o = 16; o > 0; o >>= 1) {
        s  += __shfl_xor_sync(0xffffffffu, s,  o);
        ss += __shfl_xor_sync(0xffffffffu, ss, o);
    }
    float mean = s * (1.0f / 128.0f);
    float var  = ss * (1.0f / 128.0f) - mean * mean;
    float r = rsqrtf(var + 1e-5f);
    float4 gv = ((const float4*)g1)[lane];
    float4 bv = ((const float4*)b1)[lane];
    float o0 = (mv.x - mean) * r * gv.x + bv.x;
    float o1 = (mv.y - mean) * r * gv.y + bv.y;
    float o2 = (mv.z - mean) * r * gv.z + bv.z;
    float o3 = (mv.w - mean) * r * gv.w + bv.w;

    float4 sv = ((const float4*)(src + (size_t)warp * CC))[lane];

    __half* frow = g_FIN + (size_t)warp * (2 * CC);
    ((__half2*)(frow))[lane * 2]           = __floats2half2_rn(sv.x, sv.y);
    ((__half2*)(frow))[lane * 2 + 1]       = __floats2half2_rn(sv.z, sv.w);
    ((__half2*)(frow + CC))[lane * 2]      = __floats2half2_rn(o0, o1);
    ((__half2*)(frow + CC))[lane * 2 + 1]  = __floats2half2_rn(o2, o3);
}

// ---------------- host launcher ---------------------------------------------
extern "C" void kernel_launch(void* const* d_in, const int* in_sizes, int n_in,
                              void* d_out, int out_size)
{
    const float* src = (const float*)d_in[0];
    const float* tgt = (const float*)d_in[1];
    const float* Wq  = (const float*)d_in[2];
    const float* Wk  = (const float*)d_in[3];
    const float* Wv  = (const float*)d_in[4];
    const float* Wm  = (const float*)d_in[5];
    const float* g1  = (const float*)d_in[6];
    const float* b1  = (const float*)d_in[7];
    const float* W1  = (const float*)d_in[8];
    const float* W2  = (const float*)d_in[9];
    const float* g2  = (const float*)d_in[10];
    const float* b2  = (const float*)d_in[11];

    __half *QW, *KW, *VW, *ATT, *FIN, *HIDp;
    __half *WqkvT, *WmT, *W1T, *W2T;
    float *MSG;
    cudaGetSymbolAddress((void**)&QW,    g_QW);
    cudaGetSymbolAddress((void**)&KW,    g_KW);
    cudaGetSymbolAddress((void**)&VW,    g_VW);
    cudaGetSymbolAddress((void**)&ATT,   g_ATT);
    cudaGetSymbolAddress((void**)&MSG,   g_MSG);
    cudaGetSymbolAddress((void**)&FIN,   g_FIN);
    cudaGetSymbolAddress((void**)&HIDp,  g_HID);
    cudaGetSymbolAddress((void**)&WqkvT, g_WqkvT);
    cudaGetSymbolAddress((void**)&WmT,   g_WmT);
    cudaGetSymbolAddress((void**)&W1T,   g_W1T);
    cudaGetSymbolAddress((void**)&W2T,   g_W2T);

    cudaFuncSetAttribute(gemm128<1, 1>,  cudaFuncAttributeMaxDynamicSharedMemorySize, G128_SMEM);
    cudaFuncSetAttribute(gemm128<0, 0>,  cudaFuncAttributeMaxDynamicSharedMemorySize, G128_SMEM);
    cudaFuncSetAttribute(gemm_big_gelu,  cudaFuncAttributeMaxDynamicSharedMemorySize, BIG_SMEM);
    cudaFuncSetAttribute(gemm_big_lnres, cudaFuncAttributeMaxDynamicSharedMemorySize, BIG_SMEM);
    cudaFuncSetAttribute(attn_mma,       cudaFuncAttributeMaxDynamicSharedMemorySize, AT_SMEM_BYTES);

    // 1) all weight transposes in one launch (fp32 -> fp16 [N,K])
    transpose_all<<<448, dim3(32, 8)>>>(Wq, Wk, Wv, Wm, W1, W2);

    // 2) Q+K+V projections in ONE launch (nb: 0=Q from src, 1=K, 2=V from tgt)
    gemm128<1, 1><<<dim3(3, 256), 256, G128_SMEM>>>(src, tgt, WqkvT, QW, KW, VW);

    // 3) per-window V transpose
    vtrans_kernel<<<dim3(4, 8, 128), dim3(32, 8)>>>();

    // 4) shifted-window attention (register-resident softmax; 3 CTAs/SM)
    attn_mma<<<8 * BB * NWIN, 256, AT_SMEM_BYTES>>>();

    // 5) message projection (fp32 out -> LayerNorm)
    gemm128<0, 0><<<dim3(1, 256), 256, G128_SMEM>>>(ATT, ATT, WmT, MSG, MSG, MSG);

    // 6) LN(msg) + un-shift + concat (fp16 out)
    ln_concat_kernel<<<4096, 256>>>(src, g1, b1);

    // 7) FFN1: gelu(FIN @ W1) -> HID (fp16), 64x64 warp tiles
    gemm_big_gelu<<<dim3(8, 256), 128, BIG_SMEM>>>(FIN, W1T, HIDp, HIDN, 2 * CC);

    // 8) FFN2: HID @ W2 + fused LN + residual -> d_out (fp32)
    gemm_big_lnres<<<dim3(1, 256), 128, BIG_SMEM>>>(HIDp, W2T, (float*)d_out, HIDN,
                                                    src, g2, b2);
}

// round 14
// speedup vs baseline: 1.0959x; 1.0959x over previous
#include <cuda_runtime.h>
#include <cuda_fp16.h>
#include <math.h>
#include <stdint.h>

// Problem constants
#define BB   2
#define HH   128
#define WWID 128
#define CC   128
#define NWIN 64
#define WSZ  256
#define LTOK (HH*WWID)     // 16384
#define ROWS (BB*LTOK)     // 32768
#define HIDN 1024

// ---------------- scratch ---------------------------------------------------
__device__ __half g_QW[ROWS*CC];
__device__ __half g_KW[ROWS*CC];
__device__ __half g_VWt[ROWS*CC];          // per-window transposed V: [wb][dim][key]
__device__ __half g_ATT[ROWS*CC];
__device__ float  g_MSG[ROWS*CC];          // fp32 (feeds LayerNorm)
__device__ __half g_FIN[(size_t)ROWS*2*CC];
__device__ __half g_HID[(size_t)ROWS*HIDN];
// transposed weights [N, K] in fp16
__device__ __half g_WqkvT[3*CC*CC];        // [WqT ; WkT ; WvT]
__device__ __half g_WmT[CC*CC];
__device__ __half g_W1T[HIDN*2*CC];
__device__ __half g_W2T[CC*HIDN];

// ---------------- helpers ---------------------------------------------------
__device__ __forceinline__ float gelu_exact(float x) {
    return 0.5f * x * (1.0f + erff(x * 0.70710678118654752f));
}
__device__ __forceinline__ uint32_t smem_u32(const void* p) {
    uint32_t a;
    asm("{ .reg .u64 t; cvta.to.shared.u64 t, %1; cvt.u32.u64 %0, t; }" : "=r"(a) : "l"(p));
    return a;
}
__device__ __forceinline__ void cpasync16(uint32_t dst, const __half* src) {
    asm volatile("cp.async.cg.shared.global [%0], [%1], 16;" :: "r"(dst), "l"(src));
}
#define CP_COMMIT() asm volatile("cp.async.commit_group;")
#define CP_WAIT0()  asm volatile("cp.async.wait_group 0;")
__device__ __forceinline__ void ldmx4(uint32_t addr, uint32_t& d0, uint32_t& d1,
                                      uint32_t& d2, uint32_t& d3) {
    asm volatile("ldmatrix.sync.aligned.m8n8.x4.shared.b16 {%0,%1,%2,%3}, [%4];"
                 : "=r"(d0), "=r"(d1), "=r"(d2), "=r"(d3) : "r"(addr));
}
__device__ __forceinline__ void mma_h(float* c, const uint32_t* a, uint32_t b0, uint32_t b1) {
    asm volatile("mma.sync.aligned.m16n8k16.row.col.f32.f16.f16.f32 "
                 "{%0,%1,%2,%3}, {%4,%5,%6,%7}, {%8,%9}, {%0,%1,%2,%3};"
                 : "+f"(c[0]), "+f"(c[1]), "+f"(c[2]), "+f"(c[3])
                 : "r"(a[0]), "r"(a[1]), "r"(a[2]), "r"(a[3]), "r"(b0), "r"(b1));
}

// ---------------- batched weight transpose: fp32 [R,C] -> fp16 [C,R] --------
__global__ __launch_bounds__(256) void transpose_all(const float* __restrict__ Wq,
                                                     const float* __restrict__ Wk,
                                                     const float* __restrict__ Wv,
                                                     const float* __restrict__ Wm,
                                                     const float* __restrict__ W1,
                                                     const float* __restrict__ W2)
{
    __shared__ float t[32][33];
    int id = blockIdx.x;
    const float* src; __half* dst; int R, C, bx, by;
    if (id < 64) {
        int wsel = id >> 4, tt = id & 15;
        bx = tt & 3; by = tt >> 2; R = 128; C = 128;
        src = (wsel == 0) ? Wq : (wsel == 1) ? Wk : (wsel == 2) ? Wv : Wm;
        dst = (wsel == 0) ? g_WqkvT : (wsel == 1) ? (g_WqkvT + 128 * 128)
            : (wsel == 2) ? (g_WqkvT + 2 * 128 * 128) : g_WmT;
    } else if (id < 320) {
        int tt = id - 64; bx = tt & 31; by = tt >> 5; R = 256; C = 1024;
        src = W1; dst = g_W1T;
    } else {
        int tt = id - 320; bx = tt & 3; by = tt >> 2; R = 1024; C = 128;
        src = W2; dst = g_W2T;
    }
    int tx = threadIdx.x, ty = threadIdx.y;
    int x = bx * 32 + tx;
    #pragma unroll
    for (int i = 0; i < 32; i += 8)
        t[ty + i][tx] = src[(size_t)(by * 32 + ty + i) * C + x];
    __syncthreads();
    int x2 = by * 32 + tx;
    #pragma unroll
    for (int i = 0; i < 32; i += 8)
        dst[(size_t)(bx * 32 + ty + i) * R + x2] = __float2half(t[tx][ty + i]);
}

// ---------------- one-shot K=128 GEMM ---------------------------------------
// PERM: 1 = A fp32 token layout, window-permuted rows (A0 for nb==0, A1 else).
// OUTH: 1 = fp16 out; 0 = fp32 out.
// VT:   1 = for nb==2, transpose output tile into g_VWt[wb][dim][key].
#define P1 136
#define G128_SMEM (2*128*P1*2)   // 69632

template<int PERM, int OUTH, int VT>
__global__ __launch_bounds__(256, 2) void gemm128(const void* __restrict__ A0v,
                                                  const void* __restrict__ A1v,
                                                  const __half* __restrict__ Bt,
                                                  void* __restrict__ C0v,
                                                  void* __restrict__ C1v,
                                                  void* __restrict__ C2v)
{
    extern __shared__ __half smh[];
    __half* sA  = smh;             // [128][136]
    __half* sBt = smh + 128 * P1;  // [128][136]
    int tid = threadIdx.x, wid = tid >> 5, lane = tid & 31;
    int wm = wid & 3, wn = wid >> 2;
    size_t m0 = (size_t)blockIdx.y * 128;
    int nb = blockIdx.x;

    #pragma unroll
    for (int i = 0; i < 8; i++) {
        int idx = tid + i * 256;
        int row = idx >> 4, c8 = (idx & 15) * 8;
        cpasync16(smem_u32(sBt + row * P1 + c8),
                  Bt + (size_t)(nb * 128 + row) * 128 + c8);
    }
    CP_COMMIT();

    if (PERM) {
        const float* Af = (nb == 0) ? (const float*)A0v : (const float*)A1v;
        int r2 = tid >> 1, hh = tid & 1;
        size_t m = m0 + r2;
        int b = (int)(m >> 14), win = (int)((m >> 8) & 63), pos = (int)(m & 255);
        int ip = ((win >> 3) << 4) + (pos >> 4);
        int jp = ((win & 7) << 4) + (pos & 15);
        int ii = (ip + 8) & 127, jj = (jp + 8) & 127;
        const float* srow = Af + ((size_t)b * LTOK + (size_t)ii * 128 + jj) * 128 + hh * 64;
        __half* drow = sA + r2 * P1 + hh * 64;
        #pragma unroll
        for (int q = 0; q < 16; q++) {
            float4 v = *(const float4*)(srow + q * 4);
            *(__half2*)(drow + q * 4)     = __floats2half2_rn(v.x, v.y);
            *(__half2*)(drow + q * 4 + 2) = __floats2half2_rn(v.z, v.w);
        }
    } else {
        const __half* Ah = (const __half*)A0v;
        #pragma unroll
        for (int i = 0; i < 8; i++) {
            int idx = tid + i * 256;
            int row = idx >> 4, c8 = (idx & 15) * 8;
            cpasync16(smem_u32(sA + row * P1 + c8), Ah + (m0 + row) * 128 + c8);
        }
        CP_COMMIT();
    }
    CP_WAIT0();
    __syncthreads();

    float acc[2][8][4] = {};
    int mat = lane >> 3, mr = lane & 7;
    int a_row = wm * 32 + (mat & 1) * 8 + mr;
    int a_k8  = (mat >> 1) * 8;
    int b_n   = wn * 64 + (mat >> 1) * 8 + mr;
    int b_k8  = (mat & 1) * 8;
    uint32_t uA = smem_u32(sA), uB = smem_u32(sBt);

    #pragma unroll
    for (int ks = 0; ks < 8; ks++) {
        uint32_t a[2][4], bb[4][4];
        #pragma unroll
        for (int mt = 0; mt < 2; mt++)
            ldmx4(uA + (uint32_t)(((a_row + mt * 16) * P1 + ks * 16 + a_k8) * 2),
                  a[mt][0], a[mt][1], a[mt][2], a[mt][3]);
        #pragma unroll
        for (int h = 0; h < 4; h++)
            ldmx4(uB + (uint32_t)(((b_n + h * 16) * P1 + ks * 16 + b_k8) * 2),
                  bb[h][0], bb[h][1], bb[h][2], bb[h][3]);
        #pragma unroll
        for (int mt = 0; mt < 2; mt++)
            #pragma unroll
            for (int nt = 0; nt < 8; nt++)
                mma_h(acc[mt][nt], a[mt],
                      bb[nt >> 1][(nt & 1) * 2], bb[nt >> 1][(nt & 1) * 2 + 1]);
    }

    int er = lane >> 2, ec = (lane & 3) * 2;

    if (VT && nb == 2) {
        // V path: transpose acc through smem into g_VWt[wb][dim][key]
        __syncthreads();                       // all ldmatrix reads of smem done
        __half* Vt_s = smh;                    // [128 dims][136]
        #pragma unroll
        for (int mt = 0; mt < 2; mt++) {
            int r0l = wm * 32 + mt * 16 + er;  // local key row
            #pragma unroll
            for (int nt = 0; nt < 8; nt++) {
                int c0 = wn * 64 + nt * 8 + ec;
                Vt_s[c0 * P1 + r0l]           = __float2half(acc[mt][nt][0]);
                Vt_s[(c0 + 1) * P1 + r0l]     = __float2half(acc[mt][nt][1]);
                Vt_s[c0 * P1 + r0l + 8]       = __float2half(acc[mt][nt][2]);
                Vt_s[(c0 + 1) * P1 + r0l + 8] = __float2half(acc[mt][nt][3]);
            }
        }
        __syncthreads();
        int wbw  = (int)(m0 >> 8);             // window index
        int key0 = (int)(m0 & 255);            // 0 or 128
        #pragma unroll
        for (int i = 0; i < 8; i++) {
            int idx = tid + i * 256;
            int dim = idx >> 4, c8 = (idx & 15) * 8;
            *(uint4*)(g_VWt + (size_t)wbw * 32768 + (size_t)dim * 256 + key0 + c8) =
                *(const uint4*)(Vt_s + dim * P1 + c8);
        }
        return;
    }

    void* Cv = (nb == 0) ? C0v : (nb == 1) ? C1v : C2v;
    #pragma unroll
    for (int mt = 0; mt < 2; mt++) {
        size_t r0 = m0 + wm * 32 + mt * 16 + er;
        #pragma unroll
        for (int nt = 0; nt < 8; nt++) {
            int c0 = wn * 64 + nt * 8 + ec;
            if (OUTH) {
                __half* C = (__half*)Cv;
                *(__half2*)(C + r0 * 128 + c0) =
                    __floats2half2_rn(acc[mt][nt][0], acc[mt][nt][1]);
                *(__half2*)(C + (r0 + 8) * 128 + c0) =
                    __floats2half2_rn(acc[mt][nt][2], acc[mt][nt][3]);
            } else {
                float* C = (float*)Cv;
                *(float2*)(C + r0 * 128 + c0) =
                    make_float2(acc[mt][nt][0], acc[mt][nt][1]);
                *(float2*)(C + (r0 + 8) * 128 + c0) =
                    make_float2(acc[mt][nt][2], acc[mt][nt][3]);
            }
        }
    }
}

// ---------------- big-K GEMM: 2-stage cp.async, K-chunk 64 (R12 config) -----
#define P2 72
#define ST_ELEMS (128*P2)
#define BIG_SMEM (2*2*ST_ELEMS*2)   // 73728

__device__ __forceinline__ void big_load_stage(__half* smh, int s,
                                               const __half* __restrict__ A,
                                               const __half* __restrict__ Bt,
                                               size_t m0, int n0, int K, int kc, int tid)
{
    __half* dA = smh + s * 2 * ST_ELEMS;
    __half* dB = dA + ST_ELEMS;
    #pragma unroll
    for (int i = 0; i < 4; i++) {
        int idx = tid + i * 256;
        int row = idx >> 3, c8 = (idx & 7) * 8;
        cpasync16(smem_u32(dA + row * P2 + c8), A  + (m0 + row) * (size_t)K + kc * 64 + c8);
        cpasync16(smem_u32(dB + row * P2 + c8), Bt + (size_t)(n0 + row) * K + kc * 64 + c8);
    }
    CP_COMMIT();
}

__device__ __forceinline__ void big_mainloop(__half* smh, const __half* A,
                                             const __half* Bt, size_t m0, int n0,
                                             int K, int tid, float acc[2][8][4])
{
    int lane = tid & 31, wid = tid >> 5;
    int wm = wid & 3, wn = wid >> 2;
    int mat = lane >> 3, mr = lane & 7;
    int a_row = wm * 32 + (mat & 1) * 8 + mr;
    int a_k8  = (mat >> 1) * 8;
    int b_n   = wn * 64 + (mat >> 1) * 8 + mr;
    int b_k8  = (mat & 1) * 8;
    const int nk = K >> 6;

    big_load_stage(smh, 0, A, Bt, m0, n0, K, 0, tid);

    for (int kt = 0; kt < nk; kt++) {
        CP_WAIT0();
        __syncthreads();
        if (kt + 1 < nk)
            big_load_stage(smh, (kt + 1) & 1, A, Bt, m0, n0, K, kt + 1, tid);

        int s = kt & 1;
        uint32_t uA = smem_u32(smh + s * 2 * ST_ELEMS);
        uint32_t uB = smem_u32(smh + s * 2 * ST_ELEMS + ST_ELEMS);
        #pragma unroll
        for (int ks = 0; ks < 4; ks++) {
            uint32_t a[2][4], bb[4][4];
            #pragma unroll
            for (int mt = 0; mt < 2; mt++)
                ldmx4(uA + (uint32_t)(((a_row + mt * 16) * P2 + ks * 16 + a_k8) * 2),
                      a[mt][0], a[mt][1], a[mt][2], a[mt][3]);
            #pragma unroll
            for (int h = 0; h < 4; h++)
                ldmx4(uB + (uint32_t)(((b_n + h * 16) * P2 + ks * 16 + b_k8) * 2),
                      bb[h][0], bb[h][1], bb[h][2], bb[h][3]);
            #pragma unroll
            for (int mt = 0; mt < 2; mt++)
                #pragma unroll
                for (int nt = 0; nt < 8; nt++)
                    mma_h(acc[mt][nt], a[mt],
                          bb[nt >> 1][(nt & 1) * 2], bb[nt >> 1][(nt & 1) * 2 + 1]);
        }
        __syncthreads();
    }
}

// FFN1: fp16 out with gelu
__global__ __launch_bounds__(256, 2) void gemm_big_gelu(const __half* __restrict__ A,
                                                        const __half* __restrict__ Bt,
                                                        __half* __restrict__ C,
                                                        int N, int K)
{
    extern __shared__ __half smh[];
    int tid = threadIdx.x, wid = tid >> 5, lane = tid & 31;
    int wm = wid & 3, wn = wid >> 2;
    size_t m0 = (size_t)blockIdx.y * 128;
    int n0 = blockIdx.x * 128;

    float acc[2][8][4] = {};
    big_mainloop(smh, A, Bt, m0, n0, K, tid, acc);

    int er = lane >> 2, ec = (lane & 3) * 2;
    #pragma unroll
    for (int mt = 0; mt < 2; mt++) {
        size_t r0 = m0 + wm * 32 + mt * 16 + er;
        #pragma unroll
        for (int nt = 0; nt < 8; nt++) {
            int c0 = n0 + wn * 64 + nt * 8 + ec;
            float v0 = gelu_exact(acc[mt][nt][0]);
            float v1 = gelu_exact(acc[mt][nt][1]);
            float v2 = gelu_exact(acc[mt][nt][2]);
            float v3 = gelu_exact(acc[mt][nt][3]);
            *(__half2*)(C + r0 * N + c0)       = __floats2half2_rn(v0, v1);
            *(__half2*)(C + (r0 + 8) * N + c0) = __floats2half2_rn(v2, v3);
        }
    }
}

// FFN2: fused LayerNorm + residual -> fp32 d_out (N == 128, grid.x == 1)
#define CPAD 132
__global__ __launch_bounds__(256, 2) void gemm_big_lnres(const __half* __restrict__ A,
                                                         const __half* __restrict__ Bt,
                                                         float* __restrict__ out,
                                                         int K,
                                                         const float* __restrict__ src,
                                                         const float* __restrict__ g2,
                                                         const float* __restrict__ b2)
{
    extern __shared__ __half smh[];
    int tid = threadIdx.x, wid = tid >> 5, lane = tid & 31;
    int wm = wid & 3, wn = wid >> 2;
    size_t m0 = (size_t)blockIdx.y * 128;

    float acc[2][8][4] = {};
    big_mainloop(smh, A, Bt, m0, 0, K, tid, acc);

    float* Cs = (float*)smh;   // [128][132] = 67584 B <= 73728
    int er = lane >> 2, ec = (lane & 3) * 2;
    #pragma unroll
    for (int mt = 0; mt < 2; mt++) {
        int r0l = wm * 32 + mt * 16 + er;
        #pragma unroll
        for (int nt = 0; nt < 8; nt++) {
            int c0 = wn * 64 + nt * 8 + ec;
            Cs[r0l * CPAD + c0]           = acc[mt][nt][0];
            Cs[r0l * CPAD + c0 + 1]       = acc[mt][nt][1];
            Cs[(r0l + 8) * CPAD + c0]     = acc[mt][nt][2];
            Cs[(r0l + 8) * CPAD + c0 + 1] = acc[mt][nt][3];
        }
    }
    __syncthreads();

    for (int rr = wid; rr < 128; rr += 8) {
        float4 mv = *(const float4*)(Cs + rr * CPAD + lane * 4);
        float s  = mv.x + mv.y + mv.z + mv.w;
        float ss = mv.x * mv.x + mv.y * mv.y + mv.z * mv.z + mv.w * mv.w;
        #pragma unroll
        for (int o = 16; o > 0; o >>= 1) {
            s  += __shfl_xor_sync(0xffffffffu, s,  o);
            ss += __shfl_xor_sync(0xffffffffu, ss, o);
        }
        float mean = s * (1.0f / 128.0f);
        float var  = ss * (1.0f / 128.0f) - mean * mean;
        float r = rsqrtf(var + 1e-5f);
        float4 gv = ((const float4*)g2)[lane];
        float4 bv = ((const float4*)b2)[lane];
        size_t row = m0 + rr;
        float4 sv = ((const float4*)(src + row * 128))[lane];
        float4 o4;
        o4.x = sv.x + (mv.x - mean) * r * gv.x + bv.x;
        o4.y = sv.y + (mv.y - mean) * r * gv.y + bv.y;
        o4.z = sv.z + (mv.z - mean) * r * gv.z + bv.z;
        o4.w = sv.w + (mv.w - mean) * r * gv.w + bv.w;
        ((float4*)(out + row * 128))[lane] = o4;
    }
}

// ---------------- windowed attention: register-resident scores (R12) --------
#define AQ 0
#define AK 8704
#define AP 43520
#define ARX 60416
#define ARS 60928
#define AT_SMEM_BYTES 61440

__device__ __forceinline__ int region3(int x) { return (x < 112) ? 0 : ((x < 120) ? 1 : 2); }
__device__ __forceinline__ int posid(int p, int wr, int wc) {
    return region3(wr * 16 + (p >> 4)) * 3 + region3(wc * 16 + (p & 15));
}

__global__ __launch_bounds__(256, 3) void attn_mma()
{
    extern __shared__ char sm[];
    uint32_t sB = smem_u32(sm);
    __half* Qs = (__half*)(sm + AQ);
    __half* KVs = (__half*)(sm + AK);
    __half* Ps = (__half*)(sm + AP);
    float*  Rmx = (float*)(sm + ARX);
    float*  Rsm = (float*)(sm + ARS);

    const int tid = threadIdx.x;
    const int lane = tid & 31, w = tid >> 5;
    const int wb = blockIdx.x >> 3, oct = blockIdx.x & 7;
    const int q0 = oct * 32;
    const int win = wb & 63, wr = win >> 3, wc = win & 7;
    const size_t wbase = (size_t)wb * 256 * 128;

    const int wm = w & 1, wn = w >> 1;
    const int mat = lane >> 3, mr = lane & 7;
    const int a_row = wm * 16 + (mat & 1) * 8 + mr;
    const int a_k8  = (mat >> 1) * 8;
    const int bn_off = (mat >> 1) * 8 + mr;
    const int b_k8   = (mat & 1) * 8;
    const int er = lane >> 2, ec = (lane & 3) * 2;

    #pragma unroll
    for (int i = 0; i < 2; i++) {
        int idx = tid + i * 256;
        int row = idx >> 4, c8 = (idx & 15) * 8;
        *(uint4*)(Qs + row * 136 + c8) =
            *(const uint4*)(g_QW + wbase + (size_t)(q0 + row) * 128 + c8);
    }

    const int rq = wm * 16 + er;
    const int idq0 = posid(q0 + rq, wr, wc);
    const int idq1 = posid(q0 + rq + 8, wr, wc);
    const float SC = 0.08838834764831845f;

    float sacc[2][4][4] = {};
    for (int kb = 0; kb < 2; kb++) {
        __syncthreads();
        #pragma unroll
        for (int i = 0; i < 8; i++) {
            int idx = tid + i * 256;
            int row = idx >> 4, c8 = (idx & 15) * 8;
            *(uint4*)(KVs + row * 136 + c8) =
                *(const uint4*)(g_KW + wbase + (size_t)(kb * 128 + row) * 128 + c8);
        }
        __syncthreads();

        #pragma unroll
        for (int ks = 0; ks < 8; ks++) {
            uint32_t a[4], bbf[2][4];
            ldmx4(sB + (uint32_t)(AQ + (a_row * 136 + ks * 16 + a_k8) * 2),
                  a[0], a[1], a[2], a[3]);
            #pragma unroll
            for (int h = 0; h < 2; h++)
                ldmx4(sB + (uint32_t)(AK + ((wn * 32 + h * 16 + bn_off) * 136 + ks * 16 + b_k8) * 2),
                      bbf[h][0], bbf[h][1], bbf[h][2], bbf[h][3]);
            #pragma unroll
            for (int nt = 0; nt < 4; nt++)
                mma_h(sacc[kb][nt], a, bbf[nt >> 1][(nt & 1) * 2], bbf[nt >> 1][(nt & 1) * 2 + 1]);
        }
    }

    float m0 = -1e30f, m1 = -1e30f;
    #pragma unroll
    for (int kb = 0; kb < 2; kb++)
        #pragma unroll
        for (int nt = 0; nt < 4; nt++) {
            int key = kb * 128 + wn * 32 + nt * 8 + ec;
            int idk0 = posid(key, wr, wc), idk1 = posid(key + 1, wr, wc);
            float s0 = sacc[kb][nt][0] * SC + ((idq0 == idk0) ? 0.f : -100.f);
            float s1 = sacc[kb][nt][1] * SC + ((idq0 == idk1) ? 0.f : -100.f);
            float s2 = sacc[kb][nt][2] * SC + ((idq1 == idk0) ? 0.f : -100.f);
            float s3 = sacc[kb][nt][3] * SC + ((idq1 == idk1) ? 0.f : -100.f);
            sacc[kb][nt][0] = s0; sacc[kb][nt][1] = s1;
            sacc[kb][nt][2] = s2; sacc[kb][nt][3] = s3;
            m0 = fmaxf(m0, fmaxf(s0, s1));
            m1 = fmaxf(m1, fmaxf(s2, s3));
        }
    m0 = fmaxf(m0, __shfl_xor_sync(0xffffffffu, m0, 1));
    m0 = fmaxf(m0, __shfl_xor_sync(0xffffffffu, m0, 2));
    m1 = fmaxf(m1, __shfl_xor_sync(0xffffffffu, m1, 1));
    m1 = fmaxf(m1, __shfl_xor_sync(0xffffffffu, m1, 2));
    if ((lane & 3) == 0) {
        Rmx[rq * 4 + wn]       = m0;
        Rmx[(rq + 8) * 4 + wn] = m1;
    }
    __syncthreads();
    m0 = fmaxf(fmaxf(Rmx[rq * 4 + 0], Rmx[rq * 4 + 1]),
               fmaxf(Rmx[rq * 4 + 2], Rmx[rq * 4 + 3]));
    m1 = fmaxf(fmaxf(Rmx[(rq + 8) * 4 + 0], Rmx[(rq + 8) * 4 + 1]),
               fmaxf(Rmx[(rq + 8) * 4 + 2], Rmx[(rq + 8) * 4 + 3]));

    float s0sum = 0.f, s1sum = 0.f;
    #pragma unroll
    for (int kb = 0; kb < 2; kb++)
        #pragma unroll
        for (int nt = 0; nt < 4; nt++) {
            int key = kb * 128 + wn * 32 + nt * 8 + ec;
            float e0 = __expf(sacc[kb][nt][0] - m0);
            float e1 = __expf(sacc[kb][nt][1] - m0);
            float e2 = __expf(sacc[kb][nt][2] - m1);
            float e3 = __expf(sacc[kb][nt][3] - m1);
            s0sum += e0 + e1;
            s1sum += e2 + e3;
            *(__half2*)(Ps + rq * 264 + key)       = __floats2half2_rn(e0, e1);
            *(__half2*)(Ps + (rq + 8) * 264 + key) = __floats2half2_rn(e2, e3);
        }
    s0sum += __shfl_xor_sync(0xffffffffu, s0sum, 1);
    s0sum += __shfl_xor_sync(0xffffffffu, s0sum, 2);
    s1sum += __shfl_xor_sync(0xffffffffu, s1sum, 1);
    s1sum += __shfl_xor_sync(0xffffffffu, s1sum, 2);
    if ((lane & 3) == 0) {
        Rsm[rq * 4 + wn]       = s0sum;
        Rsm[(rq + 8) * 4 + wn] = s1sum;
    }
    __syncthreads();
    float inv0 = 1.0f / (Rsm[rq * 4 + 0] + Rsm[rq * 4 + 1]
                       + Rsm[rq * 4 + 2] + Rsm[rq * 4 + 3]);
    float inv1 = 1.0f / (Rsm[(rq + 8) * 4 + 0] + Rsm[(rq + 8) * 4 + 1]
                       + Rsm[(rq + 8) * 4 + 2] + Rsm[(rq + 8) * 4 + 3]);

    float oacc[4][4] = {};
    for (int kb = 0; kb < 2; kb++) {
        if (kb) __syncthreads();
        #pragma unroll
        for (int i = 0; i < 8; i++) {
            int idx = tid + i * 256;
            int row = idx >> 4, c8 = (idx & 15) * 8;
            *(uint4*)(KVs + row * 136 + c8) =
                *(const uint4*)(g_VWt + (size_t)wb * 32768 + (size_t)row * 256 + kb * 128 + c8);
        }
        __syncthreads();

        #pragma unroll
        for (int ks = 0; ks < 8; ks++) {
            uint32_t a[4], bv[2][4];
            ldmx4(sB + (uint32_t)(AP + (a_row * 264 + kb * 128 + ks * 16 + a_k8) * 2),
                  a[0], a[1], a[2], a[3]);
            #pragma unroll
            for (int h = 0; h < 2; h++)
                ldmx4(sB + (uint32_t)(AK + ((wn * 32 + h * 16 + bn_off) * 136 + ks * 16 + b_k8) * 2),
                      bv[h][0], bv[h][1], bv[h][2], bv[h][3]);
            #pragma unroll
            for (int nt = 0; nt < 4; nt++)
                mma_h(oacc[nt], a, bv[nt >> 1][(nt & 1) * 2], bv[nt >> 1][(nt & 1) * 2 + 1]);
        }
    }

    {
        __half* op = g_ATT + wbase + (size_t)(q0 + rq) * 128;
        #pragma unroll
        for (int nt = 0; nt < 4; nt++) {
            int dim = wn * 32 + nt * 8 + ec;
            *(__half2*)(op + dim) =
                __floats2half2_rn(oacc[nt][0] * inv0, oacc[nt][1] * inv0);
            *(__half2*)(op + 8 * 128 + dim) =
                __floats2half2_rn(oacc[nt][2] * inv1, oacc[nt][3] * inv1);
        }
    }
}

// ---------------- LN(msg) + un-shift gather + concat (fp16 out) -------------
__global__ __launch_bounds__(256) void ln_concat_kernel(const float* __restrict__ src,
                                                        const float* __restrict__ g1,
                                                        const float* __restrict__ b1)
{
    int warp = (blockIdx.x * 256 + threadIdx.x) >> 5;
    int lane = threadIdx.x & 31;
    if (warp >= ROWS) return;
    int b   = warp >> 14;
    int tok = warp & 16383;
    int i = tok >> 7, j = tok & 127;
    int ip = (i + 120) & 127;
    int jp = (j + 120) & 127;
    int win = ((ip >> 4) << 3) + (jp >> 4);
    int pos = ((ip & 15) << 4) + (jp & 15);
    size_t mrow = ((size_t)b * NWIN + win) * WSZ + pos;

    float4 mv = ((const float4*)(g_MSG + mrow * CC))[lane];
    float s  = mv.x + mv.y + mv.z + mv.w;
    float ss = mv.x * mv.x + mv.y * mv.y + mv.z * mv.z + mv.w * mv.w;
    #pragma unroll
    for (int o = 16; o > 0; o >>= 1) {
        s  += __shfl_xor_sync(0xffffffffu, s,  o);
        ss += __shfl_xor_sync(0xffffffffu, ss, o);
    }
    float mean = s * (1.0f / 128.0f);
    float var  = ss * (1.0f / 128.0f) - mean * mean;
    float r = rsqrtf(var + 1e-5f);
    float4 gv = ((const float4*)g1)[lane];
    float4 bv = ((const float4*)b1)[lane];
    float o0 = (mv.x - mean) * r * gv.x + bv.x;
    float o1 = (mv.y - mean) * r * gv.y + bv.y;
    float o2 = (mv.z - mean) * r * gv.z + bv.z;
    float o3 = (mv.w - mean) * r * gv.w + bv.w;

    float4 sv = ((const float4*)(src + (size_t)warp * CC))[lane];

    __half* frow = g_FIN + (size_t)warp * (2 * CC);
    ((__half2*)(frow))[lane * 2]           = __floats2half2_rn(sv.x, sv.y);
    ((__half2*)(frow))[lane * 2 + 1]       = __floats2half2_rn(sv.z, sv.w);
    ((__half2*)(frow + CC))[lane * 2]      = __floats2half2_rn(o0, o1);
    ((__half2*)(frow + CC))[lane * 2 + 1]  = __floats2half2_rn(o2, o3);
}

// ---------------- host launcher ---------------------------------------------
extern "C" void kernel_launch(void* const* d_in, const int* in_sizes, int n_in,
                              void* d_out, int out_size)
{
    const float* src = (const float*)d_in[0];
    const float* tgt = (const float*)d_in[1];
    const float* Wq  = (const float*)d_in[2];
    const float* Wk  = (const float*)d_in[3];
    const float* Wv  = (const float*)d_in[4];
    const float* Wm  = (const float*)d_in[5];
    const float* g1  = (const float*)d_in[6];
    const float* b1  = (const float*)d_in[7];
    const float* W1  = (const float*)d_in[8];
    const float* W2  = (const float*)d_in[9];
    const float* g2  = (const float*)d_in[10];
    const float* b2  = (const float*)d_in[11];

    __half *QW, *KW, *ATT, *FIN, *HIDp;
    __half *WqkvT, *WmT, *W1T, *W2T;
    float *MSG;
    cudaGetSymbolAddress((void**)&QW,    g_QW);
    cudaGetSymbolAddress((void**)&KW,    g_KW);
    cudaGetSymbolAddress((void**)&ATT,   g_ATT);
    cudaGetSymbolAddress((void**)&MSG,   g_MSG);
    cudaGetSymbolAddress((void**)&FIN,   g_FIN);
    cudaGetSymbolAddress((void**)&HIDp,  g_HID);
    cudaGetSymbolAddress((void**)&WqkvT, g_WqkvT);
    cudaGetSymbolAddress((void**)&WmT,   g_WmT);
    cudaGetSymbolAddress((void**)&W1T,   g_W1T);
    cudaGetSymbolAddress((void**)&W2T,   g_W2T);

    cudaFuncSetAttribute(gemm128<1, 1, 1>, cudaFuncAttributeMaxDynamicSharedMemorySize, G128_SMEM);
    cudaFuncSetAttribute(gemm128<0, 0, 0>, cudaFuncAttributeMaxDynamicSharedMemorySize, G128_SMEM);
    cudaFuncSetAttribute(gemm_big_gelu,  cudaFuncAttributeMaxDynamicSharedMemorySize, BIG_SMEM);
    cudaFuncSetAttribute(gemm_big_lnres, cudaFuncAttributeMaxDynamicSharedMemorySize, BIG_SMEM);
    cudaFuncSetAttribute(attn_mma,       cudaFuncAttributeMaxDynamicSharedMemorySize, AT_SMEM_BYTES);

    // 1) all weight transposes in one launch (fp32 -> fp16 [N,K])
    transpose_all<<<448, dim3(32, 8)>>>(Wq, Wk, Wv, Wm, W1, W2);

    // 2) Q+K+V projections in ONE launch; V epilogue transposes into g_VWt
    gemm128<1, 1, 1><<<dim3(3, 256), 256, G128_SMEM>>>(src, tgt, WqkvT, QW, KW, nullptr);

    // 3) shifted-window attention (register-resident softmax; 3 CTAs/SM)
    attn_mma<<<8 * BB * NWIN, 256, AT_SMEM_BYTES>>>();

    // 4) message projection (fp32 out -> LayerNorm)
    gemm128<0, 0, 0><<<dim3(1, 256), 256, G128_SMEM>>>(ATT, ATT, WmT, MSG, MSG, MSG);

    // 5) LN(msg) + un-shift + concat (fp16 out)
    ln_concat_kernel<<<4096, 256>>>(src, g1, b1);

    // 6) FFN1: gelu(FIN @ W1) -> HID (fp16)  [R12 256-thread config]
    gemm_big_gelu<<<dim3(8, 256), 256, BIG_SMEM>>>(FIN, W1T, HIDp, HIDN, 2 * CC);

    // 7) FFN2: HID @ W2 + fused LN + residual -> d_out (fp32)
    gemm_big_lnres<<<dim3(1, 256), 256, BIG_SMEM>>>(HIDp, W2T, (float*)d_out, HIDN,
                                                    src, g2, b2);
}